// round 15
// baseline (speedup 1.0000x reference)
#include <cuda_runtime.h>
#include <cstdint>

// Problem constants (buffers sized to these; runtime sizes read from in_sizes)
#define NN 50000
#define EE 400000
#define HH 128

// ---------------- device scratch (no cudaMalloc allowed) ----------------
__device__ int   g_deg_s[20 * NN];
__device__ int   g_deg_d[20 * NN];
__device__ float g_norm_s[20 * NN];
__device__ float g_norm_d[20 * NN];
__device__ float g_h1[(size_t)5 * NN * HH];   // 128 MB: layer-1 outputs per ntype
__device__ float g_acc[(size_t)NN * HH];      // layer-2 cross-ntype accumulator
__device__ float g_y[(size_t)NN * 512];       // GEMM output (4 relation blocks)
__device__ float g_tmp[(size_t)NN * 21];      // small-feature aggregation buffer
__device__ float g_b1sum[5 * HH];
__device__ float g_b2sum[HH];
__device__ float g_msum[HH];

// dst-ntype per relation (NTYPES order: stock0, financial1, macro2, news3, policy4)
__device__ __constant__ int c_dstmap[20] = {1,2,3,4, 2,0,3,4, 0,1,3,4, 0,1,2,4, 0,2,3,1};

// ---------------- init / degrees / norms ----------------
__global__ void k_init() {
    int n = 20 * NN;
    for (int i = blockIdx.x * blockDim.x + threadIdx.x; i < n; i += gridDim.x * blockDim.x) {
        g_deg_s[i] = 0;
        g_deg_d[i] = 0;
    }
    if (blockIdx.x == 0 && threadIdx.x < HH) g_msum[threadIdx.x] = 0.0f;
}

__global__ void k_count(const int* __restrict__ edges, int E, int N) {
    int idx = blockIdx.x * blockDim.x + threadIdx.x;
    if (idx >= 20 * E) return;
    int r = idx / E;
    int e = idx - r * E;
    int s = edges[(size_t)(2 * r) * E + e];
    int d = edges[(size_t)(2 * r + 1) * E + e];
    atomicAdd(&g_deg_s[r * N + s], 1);
    atomicAdd(&g_deg_d[r * N + d], 1);
}

__global__ void k_norm(int N) {
    int idx = blockIdx.x * blockDim.x + threadIdx.x;
    if (idx >= 20 * N) return;
    int ds = g_deg_s[idx]; if (ds < 1) ds = 1;
    int dd = g_deg_d[idx]; if (dd < 1) dd = 1;
    g_norm_s[idx] = rsqrtf((float)ds);
    g_norm_d[idx] = rsqrtf((float)dd);
}

__global__ void k_bias_sums(const float* __restrict__ b1, const float* __restrict__ b2) {
    int c = threadIdx.x;  // 128 threads
    float s1[5] = {0.f, 0.f, 0.f, 0.f, 0.f};
    float s2 = 0.f;
#pragma unroll
    for (int r = 0; r < 20; r++) {
        s1[c_dstmap[r]] += b1[r * HH + c];
        s2 += b2[r * HH + c];
    }
#pragma unroll
    for (int nt = 0; nt < 5; nt++) g_b1sum[nt * HH + c] = s1[nt];
    g_b2sum[c] = s2;
}

// fill h1 (5 buffers) with summed layer-1 biases; fill acc with summed layer-2 biases
__global__ void k_fill(int N) {
    int NH = N * HH;          // 6.4M
    int tot = 6 * NH;         // 38.4M < 2^31
    int i = blockIdx.x * blockDim.x + threadIdx.x;
    if (i >= tot) return;
    int c = i & (HH - 1);
    if (i < 5 * NH) {
        int nt = i / NH;
        g_h1[i] = g_b1sum[nt * HH + c];
    } else {
        g_acc[i - 5 * NH] = g_b2sum[c];
    }
}

__global__ void k_zero_tmp(int n) {
    int i = blockIdx.x * blockDim.x + threadIdx.x;
    if (i < n) g_tmp[i] = 0.0f;
}

// ---------------- small-feature path (aggregate-first) ----------------
// tmp[dst] += x[src] * ns[src] * nd[dst]
__global__ void k_scatter_small(const float* __restrict__ x, int F, int r, int N, int E,
                                const int* __restrict__ src, const int* __restrict__ dst) {
    int e = blockIdx.x * blockDim.x + threadIdx.x;
    if (e >= E) return;
    int s = src[e];
    int d = dst[e];
    float w = g_norm_s[r * N + s] * g_norm_d[r * N + d];
    const float* xr = x + (size_t)s * F;
    float* tr = g_tmp + (size_t)d * F;
    for (int k = 0; k < F; k++) atomicAdd(tr + k, xr[k] * w);
}

// h1[out_nt] += tmp @ W   (tmp: N x F, W: F x 128)
__global__ void k_gemm_small(int F, const float* __restrict__ W, int out_nt, int N) {
    __shared__ float sW[21 * HH];
    __shared__ float sA[8][21];
    int tid = threadIdx.x;  // 128 threads
    for (int i = tid; i < F * HH; i += HH) sW[i] = W[i];
    int row0 = blockIdx.x * 8;
    for (int i = tid; i < 8 * F; i += HH) {
        int rr = i / F, k = i - rr * F;
        int r = row0 + rr;
        sA[rr][k] = (r < N) ? g_tmp[(size_t)r * F + k] : 0.0f;
    }
    __syncthreads();
    float* out = g_h1 + (size_t)out_nt * N * HH;
    int c = tid;
    for (int rr = 0; rr < 8; rr++) {
        int r = row0 + rr;
        if (r >= N) break;
        float acc = 0.0f;
        for (int k = 0; k < F; k++) acc += sA[rr][k] * sW[k * HH + c];
        out[(size_t)r * HH + c] += acc;
    }
}

// ---------------- big SGEMM: y(M,512) = A(M,K) @ [B_blk0 | B_blk1 | B_blk2 | B_blk3] ----------------
// Each 128-col block j uses B = Bbase + j*bstride (row-major K x 128).
// Inner loop uses packed fp32 pairs (fma.rn.f32x2) for 2x FFMA throughput.
#define BM 128
#define BN 128
#define BK 16
__global__ void __launch_bounds__(256, 2)
k_sgemm(const float* __restrict__ Ap, int a_sel, int M, int K,
        const float* __restrict__ Bbase, int bstride) {
    const float* A = (a_sel >= 0) ? (g_h1 + (size_t)a_sel * M * HH) : Ap;
    const float* B = Bbase + (size_t)blockIdx.y * bstride;
    const int ldc = 512;
    __shared__ __align__(16) float As[BK][BM + 4];
    __shared__ __align__(16) float Bs[BK][BN];
    int tid = threadIdx.x;
    int m0 = blockIdx.x * BM;
    int tx8 = (tid & 15) * 8;
    int ty8 = (tid >> 4) * 8;
    int arow = tid >> 2;
    int acol = (tid & 3) * 4;
    int brow = tid >> 4;
    int bcol = (tid & 15) * 8;

    unsigned long long acc[8][4];
#pragma unroll
    for (int i = 0; i < 8; i++)
#pragma unroll
        for (int j = 0; j < 4; j++) acc[i][j] = 0ULL;

    for (int k0 = 0; k0 < K; k0 += BK) {
        // load A tile (128 x 16), transposed into As[k][m]
#pragma unroll
        for (int h = 0; h < 2; h++) {
            int r = m0 + arow + h * 64;
            float4 av = make_float4(0.f, 0.f, 0.f, 0.f);
            if (r < M) av = *(const float4*)(A + (size_t)r * K + k0 + acol);
            As[acol + 0][arow + h * 64] = av.x;
            As[acol + 1][arow + h * 64] = av.y;
            As[acol + 2][arow + h * 64] = av.z;
            As[acol + 3][arow + h * 64] = av.w;
        }
        // load B tile (16 x 128)
        {
            const float* bp = B + (size_t)(k0 + brow) * HH + bcol;
            *(float4*)&Bs[brow][bcol]     = *(const float4*)bp;
            *(float4*)&Bs[brow][bcol + 4] = *(const float4*)(bp + 4);
        }
        __syncthreads();
#pragma unroll
        for (int kk = 0; kk < BK; kk++) {
            float4 a0 = *(const float4*)&As[kk][ty8];
            float4 a1 = *(const float4*)&As[kk][ty8 + 4];
            ulonglong2 b01 = *(const ulonglong2*)&Bs[kk][tx8];
            ulonglong2 b23 = *(const ulonglong2*)&Bs[kk][tx8 + 4];
            unsigned long long bb0 = b01.x, bb1 = b01.y, bb2 = b23.x, bb3 = b23.y;
            float av[8] = {a0.x, a0.y, a0.z, a0.w, a1.x, a1.y, a1.z, a1.w};
#pragma unroll
            for (int i = 0; i < 8; i++) {
                unsigned long long pa;
                asm("mov.b64 %0, {%1, %1};" : "=l"(pa) : "f"(av[i]));
                asm("fma.rn.f32x2 %0, %1, %2, %0;" : "+l"(acc[i][0]) : "l"(pa), "l"(bb0));
                asm("fma.rn.f32x2 %0, %1, %2, %0;" : "+l"(acc[i][1]) : "l"(pa), "l"(bb1));
                asm("fma.rn.f32x2 %0, %1, %2, %0;" : "+l"(acc[i][2]) : "l"(pa), "l"(bb2));
                asm("fma.rn.f32x2 %0, %1, %2, %0;" : "+l"(acc[i][3]) : "l"(pa), "l"(bb3));
            }
        }
        __syncthreads();
    }
    int cbase = blockIdx.y * BN + tx8;
#pragma unroll
    for (int i = 0; i < 8; i++) {
        int r = m0 + ty8 + i;
        if (r < M) {
            float* crow = g_y + (size_t)r * ldc + cbase;
#pragma unroll
            for (int j = 0; j < 4; j++) {
                float lo, hi;
                asm("mov.b64 {%0, %1}, %2;" : "=f"(lo), "=f"(hi) : "l"(acc[i][j]));
                crow[2 * j]     = lo;
                crow[2 * j + 1] = hi;
            }
        }
    }
}

// ---------------- 128-wide edge scatter ----------------
// out[dst] += y[src, coloff:coloff+128] * ns[src] * nd[dst]   (one warp per edge)
// out_sel: 0..4 -> g_h1 ntype buffer, 5 -> g_acc
__global__ void k_scatter128(int r, int coloff, int out_sel, int N, int E,
                             const int* __restrict__ src, const int* __restrict__ dst) {
    int gid = blockIdx.x * blockDim.x + threadIdx.x;
    int e = gid >> 5;
    if (e >= E) return;
    int lane = threadIdx.x & 31;
    int s = __ldg(&src[e]);
    int d = __ldg(&dst[e]);
    float w = __ldg(&g_norm_s[r * N + s]) * __ldg(&g_norm_d[r * N + d]);
    float4 v = *(const float4*)(g_y + (size_t)s * 512 + coloff + lane * 4);
    float* outbase = (out_sel < 5) ? (g_h1 + (size_t)out_sel * N * HH) : g_acc;
    float* o = outbase + (size_t)d * HH + lane * 4;
    float v0 = v.x * w, v1 = v.y * w, v2 = v.z * w, v3 = v.w * w;
    asm volatile("red.global.add.v2.f32 [%0], {%1, %2};" :: "l"(o),     "f"(v0), "f"(v1) : "memory");
    asm volatile("red.global.add.v2.f32 [%0], {%1, %2};" :: "l"(o + 2), "f"(v2), "f"(v3) : "memory");
}

// ---------------- final reduction + FC ----------------
__global__ void k_colsum(int N) {
    int c = threadIdx.x;  // 128 threads
    int row0 = blockIdx.x * 128;
    float s = 0.0f;
    for (int i = 0; i < 128; i++) {
        int r = row0 + i;
        if (r < N) s += g_acc[(size_t)r * HH + c];
    }
    atomicAdd(&g_msum[c], s);
}

__global__ void k_final(const float* __restrict__ Wfc, const float* __restrict__ bfc,
                        float* __restrict__ out, int N, int out_size) {
    __shared__ float m[HH];
    int t = threadIdx.x;  // 128 threads
    float mv = g_msum[t] / ((float)N * 5.0f);
    m[t] = mv;
    if (t < out_size) out[t] = mv;
    __syncthreads();
    if (t < 10 && (HH + t) < out_size) {
        float a = bfc[t];
        for (int c = 0; c < HH; c++) a += m[c] * Wfc[c * 10 + t];
        out[HH + t] = a;
    }
}

// ---------------- host launch ----------------
extern "C" void kernel_launch(void* const* d_in, const int* in_sizes, int n_in,
                              void* d_out, int out_size) {
    const float* x[5];
    for (int i = 0; i < 5; i++) x[i] = (const float*)d_in[i];
    const float* W1[5];
    for (int i = 0; i < 5; i++) W1[i] = (const float*)d_in[5 + i];
    const float* b1  = (const float*)d_in[10];
    const float* W2  = (const float*)d_in[11];
    const float* b2  = (const float*)d_in[12];
    const float* Wfc = (const float*)d_in[13];
    const float* bfc = (const float*)d_in[14];
    const int* edges = (const int*)d_in[15];

    int N = in_sizes[0] / 5;     // 50000
    int E = in_sizes[15] / 40;   // 400000
    float* out = (float*)d_out;

    static const int dstmap_h[20] = {1,2,3,4, 2,0,3,4, 0,1,3,4, 0,1,2,4, 0,2,3,1};
    static const int Fsrc[3] = {5, 16, 21};

    // degrees -> normalization factors
    k_init<<<1024, 256>>>();
    k_count<<<(20 * E + 255) / 256, 256>>>(edges, E, N);
    k_norm<<<(20 * N + 255) / 256, 256>>>(N);
    k_bias_sums<<<1, 128>>>(b1, b2);
    k_fill<<<(6 * N * HH + 255) / 256, 256>>>(N);

    // -------- layer 1: small-feature src ntypes (stock/financial/macro), aggregate-first --------
    for (int r = 0; r < 12; r++) {
        int g = r >> 2;
        int F = Fsrc[g];
        const float* W = W1[g] + (size_t)(r & 3) * F * HH;
        const int* src = edges + (size_t)(2 * r) * E;
        const int* dst = edges + (size_t)(2 * r + 1) * E;
        k_zero_tmp<<<(N * F + 255) / 256, 256>>>(N * F);
        k_scatter_small<<<(E + 255) / 256, 256>>>(x[g], F, r, N, E, src, dst);
        k_gemm_small<<<(N + 7) / 8, 128>>>(F, W, dstmap_h[r], N);
    }

    // -------- layer 1: news/policy (768-dim), GEMM-first then 128-wide scatter --------
    dim3 gemm_grid((N + BM - 1) / BM, 4);
    for (int g = 3; g < 5; g++) {
        k_sgemm<<<gemm_grid, 256>>>(x[g], -1, N, 768, W1[g], 768 * HH);
        for (int j = 0; j < 4; j++) {
            int r = 4 * g + j;
            const int* src = edges + (size_t)(2 * r) * E;
            const int* dst = edges + (size_t)(2 * r + 1) * E;
            k_scatter128<<<(E * 32 + 255) / 256, 256>>>(r, j * HH, dstmap_h[r], N, E, src, dst);
        }
    }

    // -------- layer 2: per src ntype GEMM (N=512 batched over 4 relations), scatter into acc --------
    for (int s = 0; s < 5; s++) {
        k_sgemm<<<gemm_grid, 256>>>(nullptr, s, N, HH, W2 + (size_t)4 * s * HH * HH, HH * HH);
        for (int j = 0; j < 4; j++) {
            int r = 4 * s + j;
            const int* src = edges + (size_t)(2 * r) * E;
            const int* dst = edges + (size_t)(2 * r + 1) * E;
            k_scatter128<<<(E * 32 + 255) / 256, 256>>>(r, j * HH, 5 /*acc*/, N, E, src, dst);
        }
    }

    // -------- mean + FC --------
    k_colsum<<<(N + 127) / 128, 128>>>(N);
    k_final<<<1, 128>>>(Wfc, bfc, out, N, out_size);
}

// round 16
// speedup vs baseline: 1.0016x; 1.0016x over previous
#include <cuda_runtime.h>
#include <cstdint>

// Problem constants (buffers sized to these; runtime sizes read from in_sizes)
#define NN 50000
#define EE 400000
#define HH 128

// ---------------- device scratch (no cudaMalloc allowed) ----------------
__device__ int   g_deg_s[20 * NN];
__device__ int   g_deg_d[20 * NN];
__device__ float g_norm_s[20 * NN];
__device__ float g_norm_d[20 * NN];
__device__ float g_h1[(size_t)5 * NN * HH];   // 128 MB: layer-1 outputs per ntype
__device__ float g_acc[(size_t)NN * HH];      // layer-2 cross-ntype accumulator
__device__ float g_y[(size_t)NN * 512];       // GEMM output (4 relation blocks)
__device__ float g_tmp[(size_t)NN * 21];      // small-feature aggregation buffer
__device__ float g_b1sum[5 * HH];
__device__ float g_b2sum[HH];
__device__ float g_msum[HH];

// dst-ntype per relation (NTYPES order: stock0, financial1, macro2, news3, policy4)
__device__ __constant__ int c_dstmap[20] = {1,2,3,4, 2,0,3,4, 0,1,3,4, 0,1,2,4, 0,2,3,1};

// ---------------- init / degrees / norms ----------------
__global__ void k_init() {
    int n = 20 * NN;
    for (int i = blockIdx.x * blockDim.x + threadIdx.x; i < n; i += gridDim.x * blockDim.x) {
        g_deg_s[i] = 0;
        g_deg_d[i] = 0;
    }
    if (blockIdx.x == 0 && threadIdx.x < HH) g_msum[threadIdx.x] = 0.0f;
}

__global__ void k_count(const int* __restrict__ edges, int E, int N) {
    int idx = blockIdx.x * blockDim.x + threadIdx.x;
    if (idx >= 20 * E) return;
    int r = idx / E;
    int e = idx - r * E;
    int s = edges[(size_t)(2 * r) * E + e];
    int d = edges[(size_t)(2 * r + 1) * E + e];
    atomicAdd(&g_deg_s[r * N + s], 1);
    atomicAdd(&g_deg_d[r * N + d], 1);
}

__global__ void k_norm(int N) {
    int idx = blockIdx.x * blockDim.x + threadIdx.x;
    if (idx >= 20 * N) return;
    int ds = g_deg_s[idx]; if (ds < 1) ds = 1;
    int dd = g_deg_d[idx]; if (dd < 1) dd = 1;
    g_norm_s[idx] = rsqrtf((float)ds);
    g_norm_d[idx] = rsqrtf((float)dd);
}

__global__ void k_bias_sums(const float* __restrict__ b1, const float* __restrict__ b2) {
    int c = threadIdx.x;  // 128 threads
    float s1[5] = {0.f, 0.f, 0.f, 0.f, 0.f};
    float s2 = 0.f;
#pragma unroll
    for (int r = 0; r < 20; r++) {
        s1[c_dstmap[r]] += b1[r * HH + c];
        s2 += b2[r * HH + c];
    }
#pragma unroll
    for (int nt = 0; nt < 5; nt++) g_b1sum[nt * HH + c] = s1[nt];
    g_b2sum[c] = s2;
}

// fill h1 (5 buffers) with summed layer-1 biases; fill acc with summed layer-2 biases
__global__ void k_fill(int N) {
    int NH = N * HH;          // 6.4M
    int tot = 6 * NH;         // 38.4M < 2^31
    int i = blockIdx.x * blockDim.x + threadIdx.x;
    if (i >= tot) return;
    int c = i & (HH - 1);
    if (i < 5 * NH) {
        int nt = i / NH;
        g_h1[i] = g_b1sum[nt * HH + c];
    } else {
        g_acc[i - 5 * NH] = g_b2sum[c];
    }
}

__global__ void k_zero_tmp(int n) {
    int i = blockIdx.x * blockDim.x + threadIdx.x;
    if (i < n) g_tmp[i] = 0.0f;
}

// ---------------- small-feature path (aggregate-first) ----------------
// tmp[dst] += x[src] * ns[src] * nd[dst]
__global__ void k_scatter_small(const float* __restrict__ x, int F, int r, int N, int E,
                                const int* __restrict__ src, const int* __restrict__ dst) {
    int e = blockIdx.x * blockDim.x + threadIdx.x;
    if (e >= E) return;
    int s = src[e];
    int d = dst[e];
    float w = g_norm_s[r * N + s] * g_norm_d[r * N + d];
    const float* xr = x + (size_t)s * F;
    float* tr = g_tmp + (size_t)d * F;
    for (int k = 0; k < F; k++) atomicAdd(tr + k, xr[k] * w);
}

// h1[out_nt] += tmp @ W   (tmp: N x F, W: F x 128)
__global__ void k_gemm_small(int F, const float* __restrict__ W, int out_nt, int N) {
    __shared__ float sW[21 * HH];
    __shared__ float sA[8][21];
    int tid = threadIdx.x;  // 128 threads
    for (int i = tid; i < F * HH; i += HH) sW[i] = W[i];
    int row0 = blockIdx.x * 8;
    for (int i = tid; i < 8 * F; i += HH) {
        int rr = i / F, k = i - rr * F;
        int r = row0 + rr;
        sA[rr][k] = (r < N) ? g_tmp[(size_t)r * F + k] : 0.0f;
    }
    __syncthreads();
    float* out = g_h1 + (size_t)out_nt * N * HH;
    int c = tid;
    for (int rr = 0; rr < 8; rr++) {
        int r = row0 + rr;
        if (r >= N) break;
        float acc = 0.0f;
        for (int k = 0; k < F; k++) acc += sA[rr][k] * sW[k * HH + c];
        out[(size_t)r * HH + c] += acc;
    }
}

// ---------------- big SGEMM: y(M,512) = A(M,K) @ [B_blk0 | B_blk1 | B_blk2 | B_blk3] ----------------
// Each 128-col block j uses B = Bbase + j*bstride (row-major K x 128).
// Inner loop uses packed fp32 pairs (fma.rn.f32x2) for 2x FFMA throughput.
#define BM 128
#define BN 128
#define BK 16
__global__ void __launch_bounds__(256, 2)
k_sgemm(const float* __restrict__ Ap, int a_sel, int M, int K,
        const float* __restrict__ Bbase, int bstride) {
    const float* A = (a_sel >= 0) ? (g_h1 + (size_t)a_sel * M * HH) : Ap;
    const float* B = Bbase + (size_t)blockIdx.y * bstride;
    const int ldc = 512;
    __shared__ __align__(16) float As[BK][BM + 4];
    __shared__ __align__(16) float Bs[BK][BN];
    int tid = threadIdx.x;
    int m0 = blockIdx.x * BM;
    int tx8 = (tid & 15) * 8;
    int ty8 = (tid >> 4) * 8;
    int arow = tid >> 2;
    int acol = (tid & 3) * 4;
    int brow = tid >> 4;
    int bcol = (tid & 15) * 8;

    unsigned long long acc[8][4];
#pragma unroll
    for (int i = 0; i < 8; i++)
#pragma unroll
        for (int j = 0; j < 4; j++) acc[i][j] = 0ULL;

    for (int k0 = 0; k0 < K; k0 += BK) {
        // load A tile (128 x 16), transposed into As[k][m]
#pragma unroll
        for (int h = 0; h < 2; h++) {
            int r = m0 + arow + h * 64;
            float4 av = make_float4(0.f, 0.f, 0.f, 0.f);
            if (r < M) av = *(const float4*)(A + (size_t)r * K + k0 + acol);
            As[acol + 0][arow + h * 64] = av.x;
            As[acol + 1][arow + h * 64] = av.y;
            As[acol + 2][arow + h * 64] = av.z;
            As[acol + 3][arow + h * 64] = av.w;
        }
        // load B tile (16 x 128)
        {
            const float* bp = B + (size_t)(k0 + brow) * HH + bcol;
            *(float4*)&Bs[brow][bcol]     = *(const float4*)bp;
            *(float4*)&Bs[brow][bcol + 4] = *(const float4*)(bp + 4);
        }
        __syncthreads();
#pragma unroll
        for (int kk = 0; kk < BK; kk++) {
            float4 a0 = *(const float4*)&As[kk][ty8];
            float4 a1 = *(const float4*)&As[kk][ty8 + 4];
            ulonglong2 b01 = *(const ulonglong2*)&Bs[kk][tx8];
            ulonglong2 b23 = *(const ulonglong2*)&Bs[kk][tx8 + 4];
            unsigned long long bb0 = b01.x, bb1 = b01.y, bb2 = b23.x, bb3 = b23.y;
            float av[8] = {a0.x, a0.y, a0.z, a0.w, a1.x, a1.y, a1.z, a1.w};
#pragma unroll
            for (int i = 0; i < 8; i++) {
                unsigned long long pa;
                asm("mov.b64 %0, {%1, %1};" : "=l"(pa) : "f"(av[i]));
                asm("fma.rn.f32x2 %0, %1, %2, %0;" : "+l"(acc[i][0]) : "l"(pa), "l"(bb0));
                asm("fma.rn.f32x2 %0, %1, %2, %0;" : "+l"(acc[i][1]) : "l"(pa), "l"(bb1));
                asm("fma.rn.f32x2 %0, %1, %2, %0;" : "+l"(acc[i][2]) : "l"(pa), "l"(bb2));
                asm("fma.rn.f32x2 %0, %1, %2, %0;" : "+l"(acc[i][3]) : "l"(pa), "l"(bb3));
            }
        }
        __syncthreads();
    }
    int cbase = blockIdx.y * BN + tx8;
#pragma unroll
    for (int i = 0; i < 8; i++) {
        int r = m0 + ty8 + i;
        if (r < M) {
            float* crow = g_y + (size_t)r * ldc + cbase;
#pragma unroll
            for (int j = 0; j < 4; j++) {
                float lo, hi;
                asm("mov.b64 {%0, %1}, %2;" : "=f"(lo), "=f"(hi) : "l"(acc[i][j]));
                crow[2 * j]     = lo;
                crow[2 * j + 1] = hi;
            }
        }
    }
}

// ---------------- 128-wide edge scatter ----------------
// out[dst] += y[src, coloff:coloff+128] * ns[src] * nd[dst]   (one warp per edge)
// out_sel: 0..4 -> g_h1 ntype buffer, 5 -> g_acc
__global__ void k_scatter128(int r, int coloff, int out_sel, int N, int E,
                             const int* __restrict__ src, const int* __restrict__ dst) {
    int gid = blockIdx.x * blockDim.x + threadIdx.x;
    int e = gid >> 5;
    if (e >= E) return;
    int lane = threadIdx.x & 31;
    int s = __ldg(&src[e]);
    int d = __ldg(&dst[e]);
    float w = __ldg(&g_norm_s[r * N + s]) * __ldg(&g_norm_d[r * N + d]);
    float4 v = *(const float4*)(g_y + (size_t)s * 512 + coloff + lane * 4);
    float* outbase = (out_sel < 5) ? (g_h1 + (size_t)out_sel * N * HH) : g_acc;
    float* o = outbase + (size_t)d * HH + lane * 4;
    float v0 = v.x * w, v1 = v.y * w, v2 = v.z * w, v3 = v.w * w;
    asm volatile("red.global.add.v2.f32 [%0], {%1, %2};" :: "l"(o),     "f"(v0), "f"(v1) : "memory");
    asm volatile("red.global.add.v2.f32 [%0], {%1, %2};" :: "l"(o + 2), "f"(v2), "f"(v3) : "memory");
}

// ---------------- final reduction + FC ----------------
__global__ void k_colsum(int N) {
    int c = threadIdx.x;  // 128 threads
    int row0 = blockIdx.x * 128;
    float s = 0.0f;
    for (int i = 0; i < 128; i++) {
        int r = row0 + i;
        if (r < N) s += g_acc[(size_t)r * HH + c];
    }
    atomicAdd(&g_msum[c], s);
}

__global__ void k_final(const float* __restrict__ Wfc, const float* __restrict__ bfc,
                        float* __restrict__ out, int N, int out_size) {
    __shared__ float m[HH];
    int t = threadIdx.x;  // 128 threads
    float mv = g_msum[t] / ((float)N * 5.0f);
    m[t] = mv;
    if (t < out_size) out[t] = mv;
    __syncthreads();
    if (t < 10 && (HH + t) < out_size) {
        float a = bfc[t];
        for (int c = 0; c < HH; c++) a += m[c] * Wfc[c * 10 + t];
        out[HH + t] = a;
    }
}

// ---------------- host launch ----------------
extern "C" void kernel_launch(void* const* d_in, const int* in_sizes, int n_in,
                              void* d_out, int out_size) {
    const float* x[5];
    for (int i = 0; i < 5; i++) x[i] = (const float*)d_in[i];
    const float* W1[5];
    for (int i = 0; i < 5; i++) W1[i] = (const float*)d_in[5 + i];
    const float* b1  = (const float*)d_in[10];
    const float* W2  = (const float*)d_in[11];
    const float* b2  = (const float*)d_in[12];
    const float* Wfc = (const float*)d_in[13];
    const float* bfc = (const float*)d_in[14];
    const int* edges = (const int*)d_in[15];

    int N = in_sizes[0] / 5;     // 50000
    int E = in_sizes[15] / 40;   // 400000
    float* out = (float*)d_out;

    static const int dstmap_h[20] = {1,2,3,4, 2,0,3,4, 0,1,3,4, 0,1,2,4, 0,2,3,1};
    static const int Fsrc[3] = {5, 16, 21};

    // degrees -> normalization factors
    k_init<<<1024, 256>>>();
    k_count<<<(20 * E + 255) / 256, 256>>>(edges, E, N);
    k_norm<<<(20 * N + 255) / 256, 256>>>(N);
    k_bias_sums<<<1, 128>>>(b1, b2);
    k_fill<<<(6 * N * HH + 255) / 256, 256>>>(N);

    // -------- layer 1: small-feature src ntypes (stock/financial/macro), aggregate-first --------
    for (int r = 0; r < 12; r++) {
        int g = r >> 2;
        int F = Fsrc[g];
        const float* W = W1[g] + (size_t)(r & 3) * F * HH;
        const int* src = edges + (size_t)(2 * r) * E;
        const int* dst = edges + (size_t)(2 * r + 1) * E;
        k_zero_tmp<<<(N * F + 255) / 256, 256>>>(N * F);
        k_scatter_small<<<(E + 255) / 256, 256>>>(x[g], F, r, N, E, src, dst);
        k_gemm_small<<<(N + 7) / 8, 128>>>(F, W, dstmap_h[r], N);
    }

    // -------- layer 1: news/policy (768-dim), GEMM-first then 128-wide scatter --------
    dim3 gemm_grid((N + BM - 1) / BM, 4);
    for (int g = 3; g < 5; g++) {
        k_sgemm<<<gemm_grid, 256>>>(x[g], -1, N, 768, W1[g], 768 * HH);
        for (int j = 0; j < 4; j++) {
            int r = 4 * g + j;
            const int* src = edges + (size_t)(2 * r) * E;
            const int* dst = edges + (size_t)(2 * r + 1) * E;
            k_scatter128<<<(E * 32 + 255) / 256, 256>>>(r, j * HH, dstmap_h[r], N, E, src, dst);
        }
    }

    // -------- layer 2: per src ntype GEMM (N=512 batched over 4 relations), scatter into acc --------
    for (int s = 0; s < 5; s++) {
        k_sgemm<<<gemm_grid, 256>>>(nullptr, s, N, HH, W2 + (size_t)4 * s * HH * HH, HH * HH);
        for (int j = 0; j < 4; j++) {
            int r = 4 * s + j;
            const int* src = edges + (size_t)(2 * r) * E;
            const int* dst = edges + (size_t)(2 * r + 1) * E;
            k_scatter128<<<(E * 32 + 255) / 256, 256>>>(r, j * HH, 5 /*acc*/, N, E, src, dst);
        }
    }

    // -------- mean + FC --------
    k_colsum<<<(N + 127) / 128, 128>>>(N);
    k_final<<<1, 128>>>(Wfc, bfc, out, N, out_size);
}